// round 9
// baseline (speedup 1.0000x reference)
#include <cuda_runtime.h>

#define NBINS   256
#define SUBBINS 4096
#define APAR    0.07689350249903885f  // (1/255)^2 / (2*0.01^2)
#define GRATIO  0.85745463520f        // exp(-2*APAR)
#define WSINT   6.3919026f            // sqrt(pi/APAR): interior weight sum
#define FEPS    1e-10f
#define NB      4
#define HW      262144
#define NVEC    (HW / 4)
#define GRID    148
#define GPB     37                    // blocks per batch
#define NT      512                   // threads per block
#define TAPS    27                    // +-13 bins
#define TBLN    2048                  // g-table points (1/8 bin)
// smem floats: gtab 2048 | cdp 288 | scn 256
#define SM_GTAB 0
#define SM_CDP  2048
#define SM_SCN  2336
#define SMEMB   ((2336 + 256) * 4)

// persistent scratch (zero-init at load; invariants restored in-kernel)
__device__ unsigned long long g_comb[NB * SUBBINS];   // natural sub-bin order
__device__ float              g_hist[NB * NBINS];
__device__ float              g_cdfn[NB * NBINS];
__device__ unsigned int       g_bar;
__device__ unsigned int       g_epoch;

__device__ __forceinline__ void gbar(unsigned target) {
    __syncthreads();
    if (threadIdx.x == 0) {
        __threadfence();
        atomicAdd(&g_bar, 1u);
        unsigned v;
        do {
            asm volatile("ld.global.acquire.gpu.b32 %0, [%1];"
                         : "=r"(v) : "l"(&g_bar) : "memory");
        } while (v < target);
    }
    __syncthreads();
}

__global__ __launch_bounds__(NT, 1) void fused(const float* __restrict__ x,
                                               float* __restrict__ out) {
    extern __shared__ __align__(16) float smf[];
    float* gtab = smf + SM_GTAB;
    float* cdp  = smf + SM_CDP;            // zero-padded cdfn, idx i <-> bin j=i-13
    float* scn  = smf + SM_SCN;

    const int tid   = threadIdx.x;
    const int bid   = blockIdx.x;
    const int lane  = tid & 31;
    const int warp  = tid >> 5;
    const int batch = bid / GPB;
    const int sub   = bid % GPB;

    __shared__ unsigned s_ep;
    if (tid == 0) s_ep = g_epoch;
    __syncthreads();
    const unsigned ep = s_ep;

    // ---- P1: packed sub-bin histogram via direct 64-bit RED to L2 ----
    const float4* xb = (const float4*)(x + (size_t)batch * HW);
    unsigned long long* cb = g_comb + batch * SUBBINS;
    for (int i = sub * NT + tid; i < NVEC; i += GPB * NT) {
        float4 v = xb[i];
        float vals[4] = {v.x, v.y, v.z, v.w};
        #pragma unroll
        for (int q = 0; q < 4; q++) {
            float t = vals[q] * 4080.0f;            // u*16
            int s = min((int)t, SUBBINS - 1);
            float d16 = t - (float)s - 0.5f;        // 16*dev in [-0.5,0.5]
            unsigned p = (unsigned)fmaf(d16, 1024.0f, 8192.0f);
            unsigned long long val = 0x1000000000000ull | (unsigned long long)p;
            asm volatile("red.global.add.u64 [%0], %1;"
                         :: "l"(cb + s), "l"(val) : "memory");
        }
    }
    gbar(ep + GRID);

    // ---- P2: conv -> hist (one warp per bin) ----
    {
        int wg = bid * 16 + warp;
        if (wg < NB * NBINS) {
            int b = wg >> 8, j = wg & 255;
            float h = 0.f;
            int sbase = 16 * j - 224 + lane;
            #pragma unroll
            for (int t = 0; t < 14; t++) {
                int s = sbase + t * 32;
                if ((unsigned)s < (unsigned)SUBBINS) {
                    unsigned long long cw = __ldcg(&g_comb[b * SUBBINS + s]);
                    float cnt = (float)(unsigned)(cw >> 48);
                    long long df = (long long)(cw & 0xFFFFFFFFFFFFull)
                                 - ((long long)(cw >> 48) << 13);
                    float dev = (float)df * 6.1035156e-5f;   // 2^-14
                    float d = ((float)s + 0.5f) * 0.0625f - (float)j;
                    float w = __expf(-APAR * d * d);
                    h = fmaf(cnt, w, h);
                    h = fmaf(dev, -2.0f * APAR * d * w, h);
                }
            }
            #pragma unroll
            for (int o = 16; o; o >>= 1) h += __shfl_xor_sync(0xFFFFFFFFu, h, o);
            if (lane == 0) g_hist[wg] = h;
        }
    }
    gbar(ep + 2 * GRID);

    // ---- P3: scan + cdf normalize (blocks 0..3); others re-zero g_comb ----
    if (bid < NB) {
        if (tid < NBINS) scn[tid] = __ldcg(&g_hist[bid * NBINS + tid]);
        __syncthreads();
        for (int off = 1; off < NBINS; off <<= 1) {
            float add = (tid < NBINS && tid >= off) ? scn[tid - off] : 0.f;
            __syncthreads();
            if (tid < NBINS) scn[tid] += add;
            __syncthreads();
        }
        if (tid < NBINS) {
            float S = scn[NBINS - 1];
            float invS = 1.0f / (S + FEPS);
            float c0 = scn[0] * invS;
            g_cdfn[bid * NBINS + tid] = (scn[tid] * invS - c0) / (1.0f - c0 + FEPS);
        }
    } else {
        int rb = bid - NB;
        for (int p = rb * NT + tid; p < NB * SUBBINS; p += (GRID - NB) * NT)
            g_comb[p] = 0ull;
    }
    gbar(ep + 3 * GRID);

    // ---- P4: build this batch's 2048-pt g-table in smem ----
    {
        const float* cdfn = g_cdfn + (batch << 8);
        for (int i = tid; i < 288; i += NT) {
            int j = i - 13;
            cdp[i] = ((unsigned)j < 256u) ? __ldcg(cdfn + j) : 0.f;
        }
        __syncthreads();
        #pragma unroll
        for (int it = 0; it < TBLN / NT; it++) {
            int   m  = it * NT + tid;
            int   fl = m >> 3;
            float d0 = (float)(m & 7) * 0.125f + 13.0f;
            float w  = __expf(-APAR * d0 * d0);
            float f  = __expf(fmaf(2.0f * APAR, d0, -APAR));
            const float w0 = w, f0 = f;
            float acc = 0.f;
            #pragma unroll
            for (int k = 0; k < TAPS; k++) {
                acc = fmaf(w, cdp[fl + k], acc);    // zero-padded: no predicate
                w *= f;
                f *= GRATIO;
            }
            float ws;
            if (fl >= 13 && fl <= 242) {
                ws = WSINT;                          // interior: analytic constant
            } else {
                ws = 0.f; w = w0; f = f0;
                #pragma unroll
                for (int k = 0; k < TAPS; k++) {
                    int jj = fl - 13 + k;
                    ws += ((unsigned)jj < 256u) ? w : 0.f;
                    w *= f;
                    f *= GRATIO;
                }
            }
            gtab[m] = __fdividef(acc, ws + FEPS);
        }
        __syncthreads();
    }

    // ---- P5: per-pixel linear interpolation ----
    {
        float4* ob = (float4*)(out + (size_t)batch * HW);
        for (int i = sub * NT + tid; i < NVEC; i += GPB * NT) {
            float4 v = xb[i];
            float4 o;
            float t; int ix; float fr, lo;
            t = v.x * 2040.0f; ix = (int)t; fr = t - (float)ix;
            lo = gtab[ix]; o.x = fmaf(fr, gtab[ix + 1] - lo, lo);
            t = v.y * 2040.0f; ix = (int)t; fr = t - (float)ix;
            lo = gtab[ix]; o.y = fmaf(fr, gtab[ix + 1] - lo, lo);
            t = v.z * 2040.0f; ix = (int)t; fr = t - (float)ix;
            lo = gtab[ix]; o.z = fmaf(fr, gtab[ix + 1] - lo, lo);
            t = v.w * 2040.0f; ix = (int)t; fr = t - (float)ix;
            lo = gtab[ix]; o.w = fmaf(fr, gtab[ix + 1] - lo, lo);
            ob[i] = o;
        }
    }

    if (bid == 0 && tid == 0) g_epoch = ep + 3 * GRID;
}

extern "C" void kernel_launch(void* const* d_in, const int* in_sizes, int n_in,
                              void* d_out, int out_size) {
    const float* x = (const float*)d_in[0];
    float* out = (float*)d_out;
    cudaFuncSetAttribute(fused, cudaFuncAttributeMaxDynamicSharedMemorySize, SMEMB);
    fused<<<GRID, NT, SMEMB>>>(x, out);
}

// round 10
// speedup vs baseline: 1.2095x; 1.2095x over previous
#include <cuda_runtime.h>

#define NBINS   256
#define SUBBINS 4096
#define APAR    0.07689350249903885f  // (1/255)^2 / (2*0.01^2)
#define GRATIO  0.85745463520f        // exp(-2*APAR)
#define WSINT   6.3919026f            // sqrt(pi/APAR): interior weight sum
#define FEPS    1e-10f
#define NB      4
#define HW      262144
#define NVEC    (HW / 4)
#define GRID    148
#define GPB     37                    // blocks per batch
#define NT      512                   // threads per block
#define TAPS    27                    // +-13 bins
#define TBLN    2048                  // g-table points (1/8 bin)
// smem floats: shu 4096 u32 (P1) aliased over [gtab 2048 | cdp 288 | scn 256]
#define SM_GTAB 0
#define SM_CDP  2048
#define SM_SCN  2336
#define SMEMB   (4096 * 4)

// persistent scratch (zero-init at load; invariants restored in-kernel)
__device__ unsigned long long g_comb[NB * SUBBINS];   // natural sub-bin order
__device__ float              g_hist[NB * NBINS];
__device__ float              g_cdfn[NB * NBINS];
__device__ unsigned int       g_bar;
__device__ unsigned int       g_epoch;

// transposed smem slot for conflict spreading in P1
__device__ __forceinline__ int sub_idx(int s) { return ((s & 15) << 8) | (s >> 4); }

__device__ __forceinline__ void gbar(unsigned target) {
    __syncthreads();
    if (threadIdx.x == 0) {
        __threadfence();
        atomicAdd(&g_bar, 1u);
        unsigned v;
        do {
            asm volatile("ld.global.acquire.gpu.b32 %0, [%1];"
                         : "=r"(v) : "l"(&g_bar) : "memory");
        } while (v < target);
    }
    __syncthreads();
}

__global__ __launch_bounds__(NT, 1) void fused(const float* __restrict__ x,
                                               float* __restrict__ out) {
    extern __shared__ __align__(16) float smf[];
    float*    gtab = smf + SM_GTAB;
    float*    cdp  = smf + SM_CDP;           // zero-padded cdfn, idx i <-> bin j=i-13
    float*    scn  = smf + SM_SCN;
    unsigned* shu  = (unsigned*)smf;         // P1 alias (dead before gtab build)

    const int tid   = threadIdx.x;
    const int bid   = blockIdx.x;
    const int lane  = tid & 31;
    const int warp  = tid >> 5;
    const int batch = bid / GPB;
    const int sub   = bid % GPB;

    __shared__ unsigned s_ep;
    if (tid == 0) s_ep = g_epoch;

    // ---- P1: packed sub-bin histogram (smem atomics, pre-aggregated) ----
    for (int i = tid; i < SUBBINS; i += NT) shu[i] = 0u;
    __syncthreads();
    const unsigned ep = s_ep;

    const float4* xb = (const float4*)(x + (size_t)batch * HW);
    for (int i = sub * NT + tid; i < NVEC; i += GPB * NT) {
        float4 v = xb[i];
        float vals[4] = {v.x, v.y, v.z, v.w};
        #pragma unroll
        for (int q = 0; q < 4; q++) {
            float t = vals[q] * 4080.0f;            // u*16
            int s = min((int)t, SUBBINS - 1);
            float d16 = t - (float)s - 0.5f;        // 16*dev in [-0.5,0.5]
            unsigned val = 0x100000u + (unsigned)fmaf(d16, 1024.0f, 8192.0f);
            atomicAdd(&shu[sub_idx(s)], val);
        }
    }
    __syncthreads();
    for (int i = tid; i < SUBBINS; i += NT) {
        unsigned v = shu[i];
        if (v) {
            int s = ((i & 255) << 4) | (i >> 8);    // inverse of sub_idx
            unsigned long long w = ((unsigned long long)(v >> 20) << 48)
                                 | (unsigned long long)(v & 0xFFFFFu);
            atomicAdd(&g_comb[batch * SUBBINS + s], w);
        }
    }
    gbar(ep + GRID);

    // ---- P2: conv -> hist (one warp per bin) ----
    {
        int wg = bid * 16 + warp;
        if (wg < NB * NBINS) {
            int b = wg >> 8, j = wg & 255;
            float h = 0.f;
            int sbase = 16 * j - 224 + lane;
            #pragma unroll
            for (int t = 0; t < 14; t++) {
                int s = sbase + t * 32;
                if ((unsigned)s < (unsigned)SUBBINS) {
                    unsigned long long cw = __ldcg(&g_comb[b * SUBBINS + s]);
                    float cnt = (float)(unsigned)(cw >> 48);
                    long long df = (long long)(cw & 0xFFFFFFFFFFFFull)
                                 - ((long long)(cw >> 48) << 13);
                    float dev = (float)df * 6.1035156e-5f;   // 2^-14
                    float d = ((float)s + 0.5f) * 0.0625f - (float)j;
                    float w = __expf(-APAR * d * d);
                    h = fmaf(cnt, w, h);
                    h = fmaf(dev, -2.0f * APAR * d * w, h);
                }
            }
            #pragma unroll
            for (int o = 16; o; o >>= 1) h += __shfl_xor_sync(0xFFFFFFFFu, h, o);
            if (lane == 0) g_hist[wg] = h;
        }
    }
    gbar(ep + 2 * GRID);

    // ---- P3: scan + cdf normalize (blocks 0..3); others re-zero g_comb ----
    if (bid < NB) {
        if (tid < NBINS) scn[tid] = __ldcg(&g_hist[bid * NBINS + tid]);
        __syncthreads();
        for (int off = 1; off < NBINS; off <<= 1) {
            float add = (tid < NBINS && tid >= off) ? scn[tid - off] : 0.f;
            __syncthreads();
            if (tid < NBINS) scn[tid] += add;
            __syncthreads();
        }
        if (tid < NBINS) {
            float S = scn[NBINS - 1];
            float invS = 1.0f / (S + FEPS);
            float c0 = scn[0] * invS;
            g_cdfn[bid * NBINS + tid] = (scn[tid] * invS - c0) / (1.0f - c0 + FEPS);
        }
    } else {
        int rb = bid - NB;
        for (int p = rb * NT + tid; p < NB * SUBBINS; p += (GRID - NB) * NT)
            g_comb[p] = 0ull;
    }
    gbar(ep + 3 * GRID);

    // ---- P4: build this batch's 2048-pt g-table in smem ----
    {
        const float* cdfn = g_cdfn + (batch << 8);
        for (int i = tid; i < 288; i += NT) {
            int j = i - 13;
            cdp[i] = ((unsigned)j < 256u) ? __ldcg(cdfn + j) : 0.f;
        }
        __syncthreads();
        #pragma unroll
        for (int it = 0; it < TBLN / NT; it++) {
            int   m  = it * NT + tid;
            int   fl = m >> 3;
            float d0 = (float)(m & 7) * 0.125f + 13.0f;
            float w  = __expf(-APAR * d0 * d0);
            float f  = __expf(fmaf(2.0f * APAR, d0, -APAR));
            const float w0 = w, f0 = f;
            float acc = 0.f;
            #pragma unroll
            for (int k = 0; k < TAPS; k++) {
                acc = fmaf(w, cdp[fl + k], acc);    // zero-padded: no predicate
                w *= f;
                f *= GRATIO;
            }
            float ws;
            if (fl >= 13 && fl <= 242) {
                ws = WSINT;                          // interior: analytic constant
            } else {
                ws = 0.f; w = w0; f = f0;
                #pragma unroll
                for (int k = 0; k < TAPS; k++) {
                    int jj = fl - 13 + k;
                    ws += ((unsigned)jj < 256u) ? w : 0.f;
                    w *= f;
                    f *= GRATIO;
                }
            }
            gtab[m] = __fdividef(acc, ws + FEPS);
        }
        __syncthreads();
    }

    // ---- P5: per-pixel linear interpolation ----
    {
        float4* ob = (float4*)(out + (size_t)batch * HW);
        for (int i = sub * NT + tid; i < NVEC; i += GPB * NT) {
            float4 v = xb[i];
            float4 o;
            float t; int ix; float fr, lo;
            t = v.x * 2040.0f; ix = (int)t; fr = t - (float)ix;
            lo = gtab[ix]; o.x = fmaf(fr, gtab[ix + 1] - lo, lo);
            t = v.y * 2040.0f; ix = (int)t; fr = t - (float)ix;
            lo = gtab[ix]; o.y = fmaf(fr, gtab[ix + 1] - lo, lo);
            t = v.z * 2040.0f; ix = (int)t; fr = t - (float)ix;
            lo = gtab[ix]; o.z = fmaf(fr, gtab[ix + 1] - lo, lo);
            t = v.w * 2040.0f; ix = (int)t; fr = t - (float)ix;
            lo = gtab[ix]; o.w = fmaf(fr, gtab[ix + 1] - lo, lo);
            ob[i] = o;
        }
    }

    if (bid == 0 && tid == 0) g_epoch = ep + 3 * GRID;
}

extern "C" void kernel_launch(void* const* d_in, const int* in_sizes, int n_in,
                              void* d_out, int out_size) {
    const float* x = (const float*)d_in[0];
    float* out = (float*)d_out;
    cudaFuncSetAttribute(fused, cudaFuncAttributeMaxDynamicSharedMemorySize, SMEMB);
    fused<<<GRID, NT, SMEMB>>>(x, out);
}